// round 13
// baseline (speedup 1.0000x reference)
#include <cuda_runtime.h>
#include <cuda_bf16.h>
#include <math.h>
#include <stdint.h>

// Problem constants
#define NTOK   262144          // 4096 * 64 tokens
#define CDIM   256
#define NH     8
#define HD     32
#define NWIN   64
#define MAX_LOGIT 4.6051701859880914f   // log(100)

// ---------------------------------------------------------------------------
// Scratch (static device globals — allocation-guard safe)
// ---------------------------------------------------------------------------
__device__ __align__(16) __nv_bfloat16 g_xhi[(size_t)NTOK * CDIM];
__device__ __align__(16) __nv_bfloat16 g_xlo[(size_t)NTOK * CDIM];
__device__ __align__(16) __nv_bfloat16 g_wqhi[768 * 256];
__device__ __align__(16) __nv_bfloat16 g_wqlo[768 * 256];
__device__ __align__(16) __nv_bfloat16 g_wphi[256 * 256];
__device__ __align__(16) __nv_bfloat16 g_wplo[256 * 256];
// q/k/v as bf16 hi/lo, layout [B,H,N,hd]
__device__ __align__(16) __nv_bfloat16 g_qhi[(size_t)NTOK * CDIM];
__device__ __align__(16) __nv_bfloat16 g_qlo[(size_t)NTOK * CDIM];
__device__ __align__(16) __nv_bfloat16 g_khi[(size_t)NTOK * CDIM];
__device__ __align__(16) __nv_bfloat16 g_klo[(size_t)NTOK * CDIM];
__device__ __align__(16) __nv_bfloat16 g_vhi[(size_t)NTOK * CDIM];
__device__ __align__(16) __nv_bfloat16 g_vlo[(size_t)NTOK * CDIM];
__device__ __align__(16) __nv_bfloat16 g_aohi[(size_t)NTOK * CDIM];
__device__ __align__(16) __nv_bfloat16 g_aolo[(size_t)NTOK * CDIM];

// ---------------------------------------------------------------------------
// Helpers (base-target PTX only: cp.async, ldmatrix, mma.sync)
// ---------------------------------------------------------------------------
__device__ __forceinline__ uint32_t smem_u32(const void* p) {
    uint32_t a;
    asm("{ .reg .u64 t; cvta.to.shared.u64 t, %1; cvt.u32.u64 %0, t; }"
        : "=r"(a) : "l"(p));
    return a;
}
#define CP_ASYNC16(dst, src) \
    asm volatile("cp.async.cg.shared.global [%0], [%1], 16;" \
                 :: "r"(dst), "l"(src) : "memory")
#define CP_COMMIT() asm volatile("cp.async.commit_group;" ::: "memory")
#define CP_WAIT(n)  asm volatile("cp.async.wait_group %0;" :: "n"(n) : "memory")

__device__ __forceinline__ void ldsm4(uint32_t& r0, uint32_t& r1,
                                      uint32_t& r2, uint32_t& r3, uint32_t addr) {
    asm volatile("ldmatrix.sync.aligned.m8n8.x4.shared.b16 {%0,%1,%2,%3}, [%4];"
                 : "=r"(r0), "=r"(r1), "=r"(r2), "=r"(r3) : "r"(addr));
}
__device__ __forceinline__ void ldsm4t(uint32_t& r0, uint32_t& r1,
                                       uint32_t& r2, uint32_t& r3, uint32_t addr) {
    asm volatile("ldmatrix.sync.aligned.m8n8.x4.trans.shared.b16 {%0,%1,%2,%3}, [%4];"
                 : "=r"(r0), "=r"(r1), "=r"(r2), "=r"(r3) : "r"(addr));
}
__device__ __forceinline__ void mma_bf16(float& d0, float& d1, float& d2, float& d3,
                                         uint32_t a0, uint32_t a1, uint32_t a2, uint32_t a3,
                                         uint32_t b0, uint32_t b1) {
    asm volatile("mma.sync.aligned.m16n8k16.row.col.f32.bf16.bf16.f32 "
                 "{%0,%1,%2,%3}, {%4,%5,%6,%7}, {%8,%9}, {%0,%1,%2,%3};"
                 : "+f"(d0), "+f"(d1), "+f"(d2), "+f"(d3)
                 : "r"(a0), "r"(a1), "r"(a2), "r"(a3), "r"(b0), "r"(b1));
}
__device__ __forceinline__ uint32_t pack2(float x, float y) {
    uint32_t d;
    asm("cvt.rn.bf16x2.f32 %0, %1, %2;" : "=r"(d) : "f"(y), "f"(x));
    return d;
}
__device__ __forceinline__ float bf16rt(float x) {
    return __bfloat162float(__float2bfloat16(x));
}

// ---------------------------------------------------------------------------
// fp32 -> (hi, lo) bf16 split
// ---------------------------------------------------------------------------
__global__ __launch_bounds__(256)
void split_kernel(const float* __restrict__ src,
                  __nv_bfloat16* __restrict__ hi,
                  __nv_bfloat16* __restrict__ lo, int n4)
{
    int i = blockIdx.x * 256 + threadIdx.x;
    if (i >= n4) return;
    float4 v = ((const float4*)src)[i];
    __nv_bfloat16 h0 = __float2bfloat16(v.x);
    __nv_bfloat16 h1 = __float2bfloat16(v.y);
    __nv_bfloat16 h2 = __float2bfloat16(v.z);
    __nv_bfloat16 h3 = __float2bfloat16(v.w);
    __nv_bfloat16 l0 = __float2bfloat16(v.x - __bfloat162float(h0));
    __nv_bfloat16 l1 = __float2bfloat16(v.y - __bfloat162float(h1));
    __nv_bfloat16 l2 = __float2bfloat16(v.z - __bfloat162float(h2));
    __nv_bfloat16 l3 = __float2bfloat16(v.w - __bfloat162float(h3));
    __nv_bfloat162 ha = {h0, h1}, hb = {h2, h3};
    __nv_bfloat162 la = {l0, l1}, lb = {l2, l3};
    uint2 ho, loo;
    ho.x = *(uint32_t*)&ha; ho.y = *(uint32_t*)&hb;
    loo.x = *(uint32_t*)&la; loo.y = *(uint32_t*)&lb;
    ((uint2*)hi)[i] = ho;
    ((uint2*)lo)[i] = loo;
}

// ---------------------------------------------------------------------------
// Persistent HMMA bf16 split GEMM:  [M,256] @ [Ncols,256]^T + bias
// Block tile 128x256, 512 threads (16 warps, 4x4), warp tile 32x64.
// 3-stage cp.async pipeline with prefetch distance 2, ONE barrier per chunk,
// pipeline runs across tile boundaries (persistent blocks, stride-148 tiles).
// MODE 0: fp32 C out.  MODE 1 (QKV): fused RoPE+norm+bf16 split epilogue;
// bx directly selects q/k/v type (N block = 256 = one type).
// ---------------------------------------------------------------------------
#define BKB   80            // padded bytes per 32-element bf16 row
#define A_T   10240         // 128x32 bf16 tile
#define B_T   20480         // 256x32 bf16 tile
#define STG3  61440         // AH | AL | WH | WL
#define GEMM_SMEM (3 * STG3 + 8192)   // + rope table [64][16] float2

template<int NBX, int MODE>
__global__ __launch_bounds__(512, 1)
void gemm_mma_kernel(const __nv_bfloat16* __restrict__ Ahi,
                     const __nv_bfloat16* __restrict__ Alo,
                     const __nv_bfloat16* __restrict__ Whi,
                     const __nv_bfloat16* __restrict__ Wlo,
                     const float* __restrict__ bias,
                     float* __restrict__ C, int Ncols)
{
    extern __shared__ __align__(16) char smem[];
    const uint32_t sb = smem_u32(smem);
    float2* tab = (float2*)(smem + 3 * STG3);

    const int t      = threadIdx.x;
    const int lane   = t & 31;
    const int wid    = t >> 5;
    const int warp_m = wid & 3;
    const int warp_n = wid >> 2;
    const int bid    = blockIdx.x;

    if (MODE) {
        for (int idx = t; idx < 1024; idx += 512) {
            int n = idx >> 4, i = idx & 15;
            float ang = ((float)n + 0.1f) * exp2f(-(float)i * 0.8304820237218406f);
            float s, c;
            sincosf(ang, &s, &c);
            tab[idx] = make_float2(c, s);
        }
    }

    const int ntiles = NBX * 2048;
    const int nMine  = (ntiles - bid + 147) / 148;
    const int G      = nMine * 8;

    const uint32_t a_row = lane & 15;
    const uint32_t a_kh  = (lane >> 4) & 1;
    const uint32_t b_row = (lane & 7) | ((lane >> 4) << 3);
    const uint32_t b_kh  = (lane >> 3) & 1;

    float acc[2][8][4];
#pragma unroll
    for (int i = 0; i < 2; i++)
#pragma unroll
        for (int j = 0; j < 8; j++)
#pragma unroll
            for (int q = 0; q < 4; q++) acc[i][j][q] = 0.f;

    auto load_chunk = [&](int g) {
        const int tile = bid + (g >> 3) * 148;
        const int cc   = g & 7;
        const int by   = tile / NBX;
        const int bx   = tile - by * NBX;
        const size_t Aoff = (size_t)by * (128 * 256) + cc * 32;
        const size_t Woff = (size_t)bx * (256 * 256) + cc * 32;
        const uint32_t d0 = sb + (uint32_t)(g % 3) * STG3;
        {
            int rowA = t >> 2, ca = t & 3;
            uint32_t doff = rowA * BKB + ca * 16;
            size_t   soff = (size_t)rowA * 256 + ca * 8;
            CP_ASYNC16(d0 + doff,       Ahi + Aoff + soff);
            CP_ASYNC16(d0 + A_T + doff, Alo + Aoff + soff);
        }
#pragma unroll
        for (int u = 0; u < 2; u++) {
            int idx = t + u * 512;
            int rowB = idx >> 2, cb = idx & 3;
            uint32_t doff = rowB * BKB + cb * 16;
            size_t   soff = (size_t)rowB * 256 + cb * 8;
            CP_ASYNC16(d0 + 2 * A_T + doff,       Whi + Woff + soff);
            CP_ASYNC16(d0 + 2 * A_T + B_T + doff, Wlo + Woff + soff);
        }
        CP_COMMIT();
    };

    load_chunk(0);
    if (G > 1) load_chunk(1);

    for (int g = 0; g < G; ++g) {
        if (g + 1 < G) { CP_WAIT(1); } else { CP_WAIT(0); }
        __syncthreads();
        if (g + 2 < G) load_chunk(g + 2);

        const uint32_t stg   = sb + (uint32_t)(g % 3) * STG3;
        const uint32_t baseA = stg + (warp_m * 32 + a_row) * BKB + a_kh * 16;
        const uint32_t baseB = stg + 2 * A_T + (warp_n * 64 + b_row) * BKB + b_kh * 16;

#pragma unroll
        for (int ks = 0; ks < 2; ks++) {
            uint32_t ah[2][4], al[2][4];
#pragma unroll
            for (int im = 0; im < 2; im++) {
                ldsm4(ah[im][0], ah[im][1], ah[im][2], ah[im][3],
                      baseA + im * 16 * BKB + ks * 32);
                ldsm4(al[im][0], al[im][1], al[im][2], al[im][3],
                      baseA + A_T + im * 16 * BKB + ks * 32);
            }
#pragma unroll
            for (int bnp = 0; bnp < 2; bnp++) {
                uint32_t bh[2][4], bl[2][4];
#pragma unroll
                for (int b2 = 0; b2 < 2; b2++) {
                    const int bn = bnp * 2 + b2;
                    ldsm4(bh[b2][0], bh[b2][1], bh[b2][2], bh[b2][3],
                          baseB + bn * 16 * BKB + ks * 32);
                    ldsm4(bl[b2][0], bl[b2][1], bl[b2][2], bl[b2][3],
                          baseB + B_T + bn * 16 * BKB + ks * 32);
                }
                // HH
#pragma unroll
                for (int b2 = 0; b2 < 2; b2++) {
                    const int j0 = 2 * (bnp * 2 + b2), j1 = j0 + 1;
#pragma unroll
                    for (int im = 0; im < 2; im++) {
                        mma_bf16(acc[im][j0][0], acc[im][j0][1], acc[im][j0][2], acc[im][j0][3],
                                 ah[im][0], ah[im][1], ah[im][2], ah[im][3], bh[b2][0], bh[b2][1]);
                        mma_bf16(acc[im][j1][0], acc[im][j1][1], acc[im][j1][2], acc[im][j1][3],
                                 ah[im][0], ah[im][1], ah[im][2], ah[im][3], bh[b2][2], bh[b2][3]);
                    }
                }
                // HL
#pragma unroll
                for (int b2 = 0; b2 < 2; b2++) {
                    const int j0 = 2 * (bnp * 2 + b2), j1 = j0 + 1;
#pragma unroll
                    for (int im = 0; im < 2; im++) {
                        mma_bf16(acc[im][j0][0], acc[im][j0][1], acc[im][j0][2], acc[im][j0][3],
                                 ah[im][0], ah[im][1], ah[im][2], ah[im][3], bl[b2][0], bl[b2][1]);
                        mma_bf16(acc[im][j1][0], acc[im][j1][1], acc[im][j1][2], acc[im][j1][3],
                                 ah[im][0], ah[im][1], ah[im][2], ah[im][3], bl[b2][2], bl[b2][3]);
                    }
                }
                // LH
#pragma unroll
                for (int b2 = 0; b2 < 2; b2++) {
                    const int j0 = 2 * (bnp * 2 + b2), j1 = j0 + 1;
#pragma unroll
                    for (int im = 0; im < 2; im++) {
                        mma_bf16(acc[im][j0][0], acc[im][j0][1], acc[im][j0][2], acc[im][j0][3],
                                 al[im][0], al[im][1], al[im][2], al[im][3], bh[b2][0], bh[b2][1]);
                        mma_bf16(acc[im][j1][0], acc[im][j1][1], acc[im][j1][2], acc[im][j1][3],
                                 al[im][0], al[im][1], al[im][2], al[im][3], bh[b2][2], bh[b2][3]);
                    }
                }
            }
        }

        if ((g & 7) == 7) {
            const int tile = bid + (g >> 3) * 148;
            const int by   = tile / NBX;
            const int bx   = tile - by * NBX;
            const int qr   = lane >> 2;
            const int qc2  = (lane & 3) * 2;

            if (MODE == 0) {
#pragma unroll
                for (int im = 0; im < 2; im++) {
                    const int m0 = by * 128 + warp_m * 32 + im * 16 + qr;
#pragma unroll
                    for (int nn = 0; nn < 8; nn++) {
                        const int col = bx * 256 + warp_n * 64 + nn * 8 + qc2;
                        float2 bv = *(const float2*)(bias + col);
                        float2 o0, o1;
                        o0.x = acc[im][nn][0] + bv.x;
                        o0.y = acc[im][nn][1] + bv.y;
                        o1.x = acc[im][nn][2] + bv.x;
                        o1.y = acc[im][nn][3] + bv.y;
                        *(float2*)(C + (size_t)m0 * Ncols + col)       = o0;
                        *(float2*)(C + (size_t)(m0 + 8) * Ncols + col) = o1;
                    }
                }
            } else {
                // fused RoPE + normalize + bf16 hi/lo split + scatter
                const int type = bx;     // 0 = q, 1 = k, 2 = v
                __nv_bfloat16* ohi = (type == 0) ? g_qhi : (type == 1) ? g_khi : g_vhi;
                __nv_bfloat16* olo = (type == 0) ? g_qlo : (type == 1) ? g_klo : g_vlo;
#pragma unroll
                for (int im = 0; im < 2; im++)
#pragma unroll
                    for (int hf = 0; hf < 2; hf++) {
                        const int row = by * 128 + warp_m * 32 + im * 16 + hf * 8 + qr;
                        const int n   = row & 63;
                        const int bb  = row >> 6;
#pragma unroll
                        for (int ng = 0; ng < 2; ng++) {
                            const int h = warp_n * 2 + ng;
                            float v[4][2];
#pragma unroll
                            for (int j = 0; j < 4; j++) {
                                const int nn  = ng * 4 + j;
                                const int col = bx * 256 + warp_n * 64 + nn * 8 + qc2;
                                float2 bv = *(const float2*)(bias + col);
                                v[j][0] = acc[im][nn][2 * hf]     + bv.x;
                                v[j][1] = acc[im][nn][2 * hf + 1] + bv.y;
                            }
                            if (type < 2) {
#pragma unroll
                                for (int j = 0; j < 2; j++)
#pragma unroll
                                    for (int e = 0; e < 2; e++) {
                                        const int i = j * 8 + qc2 + e;
                                        float2 cs = tab[n * 16 + i];
                                        float x1 = v[j][e], x2 = v[j + 2][e];
                                        v[j][e]     = x1 * cs.x - x2 * cs.y;
                                        v[j + 2][e] = x1 * cs.y + x2 * cs.x;
                                    }
                                float ss = 0.f;
#pragma unroll
                                for (int j = 0; j < 4; j++)
                                    ss += v[j][0] * v[j][0] + v[j][1] * v[j][1];
                                ss += __shfl_xor_sync(0xffffffffu, ss, 1);
                                ss += __shfl_xor_sync(0xffffffffu, ss, 2);
                                const float rn = 1.f / fmaxf(sqrtf(ss), 1e-12f);
#pragma unroll
                                for (int j = 0; j < 4; j++) {
                                    v[j][0] *= rn;
                                    v[j][1] *= rn;
                                }
                            }
                            const size_t obase = ((size_t)(bb * 8 + h) * 64 + n) * 32;
#pragma unroll
                            for (int j = 0; j < 4; j++) {
                                const int d = j * 8 + qc2;
                                float x0 = v[j][0], x1 = v[j][1];
                                float h0 = bf16rt(x0), h1 = bf16rt(x1);
                                *(uint32_t*)(ohi + obase + d) = pack2(x0, x1);
                                *(uint32_t*)(olo + obase + d) = pack2(x0 - h0, x1 - h1);
                            }
                        }
                    }
            }
#pragma unroll
            for (int i = 0; i < 2; i++)
#pragma unroll
                for (int j = 0; j < 8; j++)
#pragma unroll
                    for (int q = 0; q < 4; q++) acc[i][j][q] = 0.f;
        }
    }
}

// ---------------------------------------------------------------------------
// HMMA attention: one block per (b, head-pair), 256 threads = 8 warps.
// h2 = wid>>2 selects the head within the pair; wq = wid&3 the 16-row slice.
// Mask staged once per block (shared by both heads).
// ---------------------------------------------------------------------------
#define ATS 80                          // padded bytes per 32-bf16 row
#define HREG 30720                      // per-head region (6 tiles x 5120)
#define AQ_HI 0
#define AQ_LO 5120
#define AK_HI 10240
#define AK_LO 15360
#define AV_HI 20480
#define AV_LO 25600
#define AMASK 61440                     // 64 rows x 68 floats (272B rows)
#define ATT_SMEM 78848

__global__ __launch_bounds__(256)
void attn_mma_kernel(const float* __restrict__ mask, const float* __restrict__ ls)
{
    extern __shared__ __align__(16) char smx[];
    const uint32_t sb = smem_u32(smx);

    const int bid  = blockIdx.x;
    const int b    = bid >> 2;
    const int hp   = bid & 3;
    const int w    = b & (NWIN - 1);
    const int t    = threadIdx.x;
    const int lane = t & 31;
    const int wid  = t >> 5;
    const int h2   = wid >> 2;
    const int wq   = wid & 3;

    // stage q/k/v hi/lo for both heads + mask once
    {
        const int row = t >> 2, c = t & 3;      // 256 16B chunks per tile
#pragma unroll
        for (int hh = 0; hh < 2; hh++) {
            const size_t basehh = (size_t)(b * 8 + hp * 2 + hh) * 2048;
            const __nv_bfloat16* srcs[6] = { g_qhi + basehh, g_qlo + basehh,
                                             g_khi + basehh, g_klo + basehh,
                                             g_vhi + basehh, g_vlo + basehh };
            const uint32_t dst0 = sb + hh * HREG;
#pragma unroll
            for (int tl = 0; tl < 6; tl++)
                CP_ASYNC16(dst0 + tl * 5120 + row * ATS + c * 16,
                           srcs[tl] + (size_t)row * 32 + c * 8);
        }
        const float* msrc = mask + (size_t)w * 4096;
#pragma unroll
        for (int u = 0; u < 4; u++) {
            int idx = t + u * 256;
            int mr = idx >> 4, c4 = idx & 15;
            CP_ASYNC16(sb + AMASK + mr * 272 + c4 * 16,
                       msrc + (size_t)mr * 64 + c4 * 4);
        }
        CP_COMMIT();
        CP_WAIT(0);
    }
    const int h = hp * 2 + h2;
    const float scale = __expf(fminf(ls[h], MAX_LOGIT));
    __syncthreads();

    const uint32_t sbh = sb + h2 * HREG;
    const uint32_t a_row = lane & 15;
    const uint32_t a_kh  = (lane >> 4) & 1;
    const uint32_t b_row = (lane & 7) | (((lane >> 4) & 1) << 3);
    const uint32_t b_kh  = (lane >> 3) & 1;

    uint32_t aqh[2][4], aql[2][4];
#pragma unroll
    for (int ks = 0; ks < 2; ks++) {
        uint32_t off = (wq * 16 + a_row) * ATS + a_kh * 16 + ks * 32;
        ldsm4(aqh[ks][0], aqh[ks][1], aqh[ks][2], aqh[ks][3], sbh + AQ_HI + off);
        ldsm4(aql[ks][0], aql[ks][1], aql[ks][2], aql[ks][3], sbh + AQ_LO + off);
    }

    float S[8][4];
#pragma unroll
    for (int j = 0; j < 8; j++)
#pragma unroll
        for (int q = 0; q < 4; q++) S[j][q] = 0.f;

#pragma unroll
    for (int ks = 0; ks < 2; ks++)
#pragma unroll
        for (int nh = 0; nh < 4; nh++) {
            uint32_t off = (nh * 16 + b_row) * ATS + b_kh * 16 + ks * 32;
            uint32_t bh[4], bl[4];
            ldsm4(bh[0], bh[1], bh[2], bh[3], sbh + AK_HI + off);
            ldsm4(bl[0], bl[1], bl[2], bl[3], sbh + AK_LO + off);
            const int j0 = 2 * nh, j1 = 2 * nh + 1;
            mma_bf16(S[j0][0], S[j0][1], S[j0][2], S[j0][3],
                     aqh[ks][0], aqh[ks][1], aqh[ks][2], aqh[ks][3], bh[0], bh[1]);
            mma_bf16(S[j1][0], S[j1][1], S[j1][2], S[j1][3],
                     aqh[ks][0], aqh[ks][1], aqh[ks][2], aqh[ks][3], bh[2], bh[3]);
            mma_bf16(S[j0][0], S[j0][1], S[j0][2], S[j0][3],
                     aqh[ks][0], aqh[ks][1], aqh[ks][2], aqh[ks][3], bl[0], bl[1]);
            mma_bf16(S[j1][0], S[j1][1], S[j1][2], S[j1][3],
                     aqh[ks][0], aqh[ks][1], aqh[ks][2], aqh[ks][3], bl[2], bl[3]);
            mma_bf16(S[j0][0], S[j0][1], S[j0][2], S[j0][3],
                     aql[ks][0], aql[ks][1], aql[ks][2], aql[ks][3], bh[0], bh[1]);
            mma_bf16(S[j1][0], S[j1][1], S[j1][2], S[j1][3],
                     aql[ks][0], aql[ks][1], aql[ks][2], aql[ks][3], bh[2], bh[3]);
        }

    const int qr = lane >> 2;
    const int qc = lane & 3;
    const float* smaskf = (const float*)(smx + AMASK);
#pragma unroll
    for (int hf = 0; hf < 2; hf++) {
        const int r = wq * 16 + qr + hf * 8;
        float v[16];
        float mx = -1e30f;
#pragma unroll
        for (int j = 0; j < 8; j++) {
            float2 mv = *(const float2*)(smaskf + r * 68 + j * 8 + qc * 2);
            v[2 * j]     = S[j][2 * hf]     * scale + mv.x;
            v[2 * j + 1] = S[j][2 * hf + 1] * scale + mv.y;
            mx = fmaxf(mx, fmaxf(v[2 * j], v[2 * j + 1]));
        }
        mx = fmaxf(mx, __shfl_xor_sync(0xffffffffu, mx, 1));
        mx = fmaxf(mx, __shfl_xor_sync(0xffffffffu, mx, 2));
        float sum = 0.f;
#pragma unroll
        for (int e = 0; e < 16; e++) { v[e] = __expf(v[e] - mx); sum += v[e]; }
        sum += __shfl_xor_sync(0xffffffffu, sum, 1);
        sum += __shfl_xor_sync(0xffffffffu, sum, 2);
        const float inv = 1.f / sum;
#pragma unroll
        for (int j = 0; j < 8; j++) {
            S[j][2 * hf]     = v[2 * j] * inv;
            S[j][2 * hf + 1] = v[2 * j + 1] * inv;
        }
    }

    float O[4][4];
#pragma unroll
    for (int j = 0; j < 4; j++)
#pragma unroll
        for (int q = 0; q < 4; q++) O[j][q] = 0.f;

#pragma unroll
    for (int j16 = 0; j16 < 4; j16++) {
        uint32_t aph[4], apl[4];
#pragma unroll
        for (int u = 0; u < 2; u++) {
            const int jt = 2 * j16 + u;
            float p0 = S[jt][0], p1 = S[jt][1], p2 = S[jt][2], p3 = S[jt][3];
            float h0 = bf16rt(p0), h1 = bf16rt(p1), h2f = bf16rt(p2), h3 = bf16rt(p3);
            aph[2 * u]     = pack2(p0, p1);
            aph[2 * u + 1] = pack2(p2, p3);
            apl[2 * u]     = pack2(p0 - h0, p1 - h1);
            apl[2 * u + 1] = pack2(p2 - h2f, p3 - h3);
        }
        const uint32_t vrow = j16 * 16 + ((lane >> 3) & 1) * 8 + (lane & 7);
#pragma unroll
        for (int nhh = 0; nhh < 2; nhh++) {
            const uint32_t voff = vrow * ATS + (nhh * 16 + ((lane >> 4) & 1) * 8) * 2;
            uint32_t bh[4], bl[4];
            ldsm4t(bh[0], bh[1], bh[2], bh[3], sbh + AV_HI + voff);
            ldsm4t(bl[0], bl[1], bl[2], bl[3], sbh + AV_LO + voff);
            const int n0 = 2 * nhh, n1 = 2 * nhh + 1;
            mma_bf16(O[n0][0], O[n0][1], O[n0][2], O[n0][3],
                     aph[0], aph[1], aph[2], aph[3], bh[0], bh[1]);
            mma_bf16(O[n1][0], O[n1][1], O[n1][2], O[n1][3],
                     aph[0], aph[1], aph[2], aph[3], bh[2], bh[3]);
            mma_bf16(O[n0][0], O[n0][1], O[n0][2], O[n0][3],
                     aph[0], aph[1], aph[2], aph[3], bl[0], bl[1]);
            mma_bf16(O[n1][0], O[n1][1], O[n1][2], O[n1][3],
                     aph[0], aph[1], aph[2], aph[3], bl[2], bl[3]);
            mma_bf16(O[n0][0], O[n0][1], O[n0][2], O[n0][3],
                     apl[0], apl[1], apl[2], apl[3], bh[0], bh[1]);
            mma_bf16(O[n1][0], O[n1][1], O[n1][2], O[n1][3],
                     apl[0], apl[1], apl[2], apl[3], bh[2], bh[3]);
        }
    }

#pragma unroll
    for (int nt = 0; nt < 4; nt++)
#pragma unroll
        for (int hf = 0; hf < 2; hf++) {
            const int row = b * 64 + wq * 16 + qr + hf * 8;
            const int col = h * 32 + nt * 8 + qc * 2;
            const size_t oi = (size_t)row * 256 + col;
            float x0 = O[nt][2 * hf], x1 = O[nt][2 * hf + 1];
            float h0 = bf16rt(x0),    h1 = bf16rt(x1);
            *(uint32_t*)(g_aohi + oi) = pack2(x0, x1);
            *(uint32_t*)(g_aolo + oi) = pack2(x0 - h0, x1 - h1);
        }
}

// ---------------------------------------------------------------------------
// Launch
// ---------------------------------------------------------------------------
extern "C" void kernel_launch(void* const* d_in, const int* in_sizes, int n_in,
                              void* d_out, int out_size)
{
    const float* x      = (const float*)d_in[0];
    const float* mask   = (const float*)d_in[1];
    const float* qkv_w  = (const float*)d_in[2];
    const float* qkv_b  = (const float*)d_in[3];
    const float* proj_w = (const float*)d_in[4];
    const float* proj_b = (const float*)d_in[5];
    const float* ls     = (const float*)d_in[6];

    __nv_bfloat16 *p_xhi, *p_xlo, *p_wqhi, *p_wqlo, *p_wphi, *p_wplo, *p_aohi, *p_aolo;
    cudaGetSymbolAddress((void**)&p_xhi,  g_xhi);
    cudaGetSymbolAddress((void**)&p_xlo,  g_xlo);
    cudaGetSymbolAddress((void**)&p_wqhi, g_wqhi);
    cudaGetSymbolAddress((void**)&p_wqlo, g_wqlo);
    cudaGetSymbolAddress((void**)&p_wphi, g_wphi);
    cudaGetSymbolAddress((void**)&p_wplo, g_wplo);
    cudaGetSymbolAddress((void**)&p_aohi, g_aohi);
    cudaGetSymbolAddress((void**)&p_aolo, g_aolo);

    cudaFuncSetAttribute(gemm_mma_kernel<3, 1>,
                         cudaFuncAttributeMaxDynamicSharedMemorySize, GEMM_SMEM);
    cudaFuncSetAttribute(gemm_mma_kernel<1, 0>,
                         cudaFuncAttributeMaxDynamicSharedMemorySize, GEMM_SMEM);
    cudaFuncSetAttribute(attn_mma_kernel,
                         cudaFuncAttributeMaxDynamicSharedMemorySize, ATT_SMEM);

    // 0) split inputs / weights to bf16 hi/lo
    split_kernel<<<(NTOK * CDIM / 4 + 255) / 256, 256>>>(x, p_xhi, p_xlo, NTOK * CDIM / 4);
    split_kernel<<<(768 * 256 / 4 + 255) / 256, 256>>>(qkv_w, p_wqhi, p_wqlo, 768 * 256 / 4);
    split_kernel<<<(256 * 256 / 4 + 255) / 256, 256>>>(proj_w, p_wphi, p_wplo, 256 * 256 / 4);

    // 1) QKV GEMM (persistent) + fused RoPE/norm/split epilogue
    gemm_mma_kernel<3, 1><<<148, 512, GEMM_SMEM>>>(
        p_xhi, p_xlo, p_wqhi, p_wqlo, qkv_b, nullptr, 768);

    // 2) attention: one block per (b, head-pair)
    attn_mma_kernel<<<4096 * 4, 256, ATT_SMEM>>>(mask, ls);

    // 3) proj GEMM (persistent): [262144,256] @ [256,256]^T -> out
    gemm_mma_kernel<1, 0><<<148, 512, GEMM_SMEM>>>(
        p_aohi, p_aolo, p_wphi, p_wplo, proj_b, (float*)d_out, 256);
}